// round 14
// baseline (speedup 1.0000x reference)
#include <cuda_runtime.h>
#include <cuda_bf16.h>
#include <cstdint>

// Problem dims (fixed): B=1, S=128, L=256, D=256, H=8, C=32
#define S_ 128
#define L_ 256
#define D_ 256
#define H_ 8
#define C_ 32
#define MROWS (S_ * L_)          // 32768
#define LOG2E 1.4426950408889634f
#define NEG_BIAS2 (-10000.0f * LOG2E)
#define QSCALE (0.17677669529663687f * LOG2E)  // (1/sqrt(32)) * log2(e)

// ---------------- scratch (device globals; no cudaMalloc allowed) ----------
__device__ __nv_bfloat16 g_mnh[MROWS * D_];
__device__ __nv_bfloat16 g_mnl[MROWS * D_];
__device__ __nv_bfloat16 g_wh[5 * D_ * D_];   // [Wq|Wk|Wv|Wg|Wo] hi
__device__ __nv_bfloat16 g_wl[5 * D_ * D_];   // lo
__device__ float g_q[MROWS * D_];    // [s][h][l][c], pre-scaled by QSCALE
__device__ float g_k[MROWS * D_];
__device__ float g_v[MROWS * D_];
__device__ float g_g[MROWS * D_];
__device__ __nv_bfloat16 g_oh[MROWS * D_];    // attn out hi, [s][l][h*32+c]
__device__ __nv_bfloat16 g_ol[MROWS * D_];
__device__ float g_sp[L_];
__device__ float g_rp[L_];

__device__ __forceinline__ float fast_exp2(float x) {
    float y;
    asm("ex2.approx.ftz.f32 %0, %1;" : "=f"(y) : "f"(x));
    return y;
}
__device__ __forceinline__ uint32_t smem_u32(const void* p) {
    uint32_t a;
    asm("{ .reg .u64 t; cvta.to.shared.u64 t, %1; cvt.u32.u64 %0, t; }" : "=r"(a) : "l"(p));
    return a;
}
__device__ __forceinline__ void ldsm4(uint32_t* r, uint32_t addr) {
    asm volatile("ldmatrix.sync.aligned.m8n8.x4.shared.b16 {%0,%1,%2,%3}, [%4];"
                 : "=r"(r[0]), "=r"(r[1]), "=r"(r[2]), "=r"(r[3]) : "r"(addr));
}
__device__ __forceinline__ void mma_bf16(float* c, const uint32_t* a, uint32_t b0,
                                         uint32_t b1) {
    asm volatile(
        "mma.sync.aligned.m16n8k16.row.col.f32.bf16.bf16.f32 "
        "{%0,%1,%2,%3}, {%4,%5,%6,%7}, {%8,%9}, {%0,%1,%2,%3};"
        : "+f"(c[0]), "+f"(c[1]), "+f"(c[2]), "+f"(c[3])
        : "r"(a[0]), "r"(a[1]), "r"(a[2]), "r"(a[3]), "r"(b0), "r"(b1));
}
__device__ __forceinline__ void cp16(uint32_t smaddr, const void* gptr) {
    asm volatile("cp.async.cg.shared.global [%0], [%1], 16;" :: "r"(smaddr), "l"(gptr));
}
#define CP_COMMIT() asm volatile("cp.async.commit_group;" ::: "memory")
#define CP_WAIT0()  asm volatile("cp.async.wait_group 0;" ::: "memory")

// ---------------- mask prep: dtype-agnostic (bool8 / int32 / float32) ------
__global__ void prep_mask_kernel(const void* sp_raw, const void* rp_raw) {
    __shared__ int flagF, flagOff;
    int tid = threadIdx.x;  // 256
    if (tid == 0) { flagF = 0; flagOff = 0; }
    __syncthreads();
    const unsigned char* pb = (const unsigned char*)sp_raw;
    const unsigned char* qb = (const unsigned char*)rp_raw;
    unsigned char b1 = pb[tid], b2 = qb[tid];
    if ((tid & 3) == 3 && (b1 == 0x3F || b2 == 0x3F)) atomicOr(&flagF, 1);
    if ((tid & 3) != 0 && (b1 != 0 || b2 != 0)) atomicOr(&flagOff, 1);
    __syncthreads();
    int mode = flagF ? 2 : (flagOff ? 0 : 1);
    float vs, vr;
    if (mode == 0) {
        vs = (((const unsigned char*)sp_raw)[tid] != 0) ? 1.f : 0.f;
        vr = (((const unsigned char*)rp_raw)[tid] != 0) ? 1.f : 0.f;
    } else if (mode == 1) {
        vs = (((const int*)sp_raw)[tid] != 0) ? 1.f : 0.f;
        vr = (((const int*)rp_raw)[tid] != 0) ? 1.f : 0.f;
    } else {
        vs = (((const float*)sp_raw)[tid] != 0.f) ? 1.f : 0.f;
        vr = (((const float*)rp_raw)[tid] != 0.f) ? 1.f : 0.f;
    }
    g_sp[tid] = vs;
    g_rp[tid] = vr;
}

// ---------------- weight prep: fp32 -> bf16 hi/lo --------------------------
__global__ __launch_bounds__(256) void prep_w_kernel(
    const float* __restrict__ Wq, const float* __restrict__ Wk,
    const float* __restrict__ Wv, const float* __restrict__ Wg,
    const float* __restrict__ Wo) {
    int row = blockIdx.x;      // 0..1279
    int tid = threadIdx.x;
    int t = row >> 8;
    const float* W = (t == 0) ? Wq : (t == 1) ? Wk : (t == 2) ? Wv : (t == 3) ? Wg : Wo;
    float v = W[(size_t)(row & 255) * D_ + tid];
    __nv_bfloat16 hi = __float2bfloat16(v);
    __nv_bfloat16 lo = __float2bfloat16(v - __bfloat162float(hi));
    g_wh[(size_t)row * D_ + tid] = hi;
    g_wl[(size_t)row * D_ + tid] = lo;
}

// ---------------- LayerNorm: warp per row -> bf16 hi/lo --------------------
__global__ __launch_bounds__(256) void ln_kernel(const float* __restrict__ m,
                                                 const float* __restrict__ gam,
                                                 const float* __restrict__ bet) {
    int row = blockIdx.x * 8 + (threadIdx.x >> 5);
    int lane = threadIdx.x & 31;
    const float4* src = (const float4*)(m + (size_t)row * D_);
    float4 a = src[lane], b = src[lane + 32];
    float s1 = a.x + a.y + a.z + a.w + b.x + b.y + b.z + b.w;
    float s2 = a.x * a.x + a.y * a.y + a.z * a.z + a.w * a.w +
               b.x * b.x + b.y * b.y + b.z * b.z + b.w * b.w;
    #pragma unroll
    for (int o = 16; o > 0; o >>= 1) {
        s1 += __shfl_xor_sync(0xFFFFFFFFu, s1, o);
        s2 += __shfl_xor_sync(0xFFFFFFFFu, s2, o);
    }
    float mu = s1 * (1.f / D_);
    float rstd = rsqrtf(s2 * (1.f / D_) - mu * mu + 1e-5f);
    float va[8] = {a.x, a.y, a.z, a.w, b.x, b.y, b.z, b.w};
    #pragma unroll
    for (int i = 0; i < 8; i++) {
        int c = (i < 4) ? (lane * 4 + i) : (128 + lane * 4 + i - 4);
        float y = (va[i] - mu) * rstd * gam[c] + bet[c];
        __nv_bfloat16 hi = __float2bfloat16(y);
        __nv_bfloat16 lo = __float2bfloat16(y - __bfloat162float(hi));
        g_mnh[(size_t)row * D_ + c] = hi;
        g_mnl[(size_t)row * D_ + c] = lo;
    }
}

// ---------------- mma.sync GEMM: C[128x64] = A[128x256] * B[64x256]^T ------
// bf16x3: hi*hi + hi*lo + lo*hi, fp32 accumulators. Fragments loaded ONCE per
// k16 step, all 3 passes run from registers. Warps tiled 4m x 2n (32x32 each).
// 2 CTAs/SM via __launch_bounds__(256,2); cp.async.cg smem fills.
#define PADK 72
#define OFF_AH 0
#define OFF_AL (128 * PADK)
#define OFF_BH (2 * 128 * PADK)
#define OFF_BL (2 * 128 * PADK + 64 * PADK)
#define SM_GEMM_HALVES (2 * 128 * PADK + 2 * 64 * PADK)   // 27648 halves = 55296 B

__global__ __launch_bounds__(256, 2) void gemm_kernel(
    const __nv_bfloat16* __restrict__ Ah, const __nv_bfloat16* __restrict__ Al,
    const __nv_bfloat16* __restrict__ Bh, const __nv_bfloat16* __restrict__ Bl,
    const float* __restrict__ bias, float* __restrict__ outp, int mode) {
    extern __shared__ __align__(16) __nv_bfloat16 sm[];
    uint32_t smb = smem_u32(sm);
    int tid = threadIdx.x;
    int wid = tid >> 5, lane = tid & 31;
    int wm = wid & 3, wn = wid >> 2;
    int bm = blockIdx.y * 128;
    int bn0 = blockIdx.x * 64;

    const __nv_bfloat16* A0 = Ah + (size_t)bm * D_;
    const __nv_bfloat16* A1 = Al + (size_t)bm * D_;
    const __nv_bfloat16* B0 = Bh + (size_t)bn0 * D_;
    const __nv_bfloat16* B1 = Bl + (size_t)bn0 * D_;

    float acc[2][4][4];
    #pragma unroll
    for (int i = 0; i < 2; i++)
        #pragma unroll
        for (int f = 0; f < 4; f++)
            #pragma unroll
            for (int e = 0; e < 4; e++) acc[i][f][e] = 0.f;

    uint32_t aKof = (lane >> 4) * 8;
    uint32_t bN = (lane & 7) + ((lane >> 4) << 3);
    uint32_t bKof = ((lane >> 3) & 1) * 8;

    for (int k0 = 0; k0 < D_; k0 += 64) {
        if (k0) __syncthreads();   // prior chunk's reads done before overwrite
        // fill: A 128x64 hi+lo (1024 x 16B each), B 64x64 hi+lo (512 each)
        #pragma unroll
        for (int t = 0; t < 4; t++) {
            int i = tid + t * 256;
            int r = i >> 3, sg = i & 7;
            uint32_t d = smb + (uint32_t)(r * PADK + sg * 8) * 2;
            const __nv_bfloat16* s = A0 + (size_t)r * D_ + k0 + sg * 8;
            cp16(d + OFF_AH * 2, s);
            cp16(d + OFF_AL * 2, A1 + (s - A0));
        }
        #pragma unroll
        for (int t = 0; t < 2; t++) {
            int i = tid + t * 256;
            int r = i >> 3, sg = i & 7;
            uint32_t d = smb + (uint32_t)(r * PADK + sg * 8) * 2;
            const __nv_bfloat16* s = B0 + (size_t)r * D_ + k0 + sg * 8;
            cp16(d + OFF_BH * 2, s);
            cp16(d + OFF_BL * 2, B1 + (s - B0));
        }
        CP_COMMIT();
        CP_WAIT0();
        __syncthreads();

        #pragma unroll
        for (int ks = 0; ks < 4; ks++) {
            uint32_t ah[2][4], al[2][4], bh[2][4], bl[2][4];
            #pragma unroll
            for (int mf = 0; mf < 2; mf++) {
                uint32_t r = wm * 32 + mf * 16 + (lane & 15);
                uint32_t off = (r * PADK + ks * 16 + aKof) * 2;
                ldsm4(ah[mf], smb + OFF_AH * 2 + off);
                ldsm4(al[mf], smb + OFF_AL * 2 + off);
            }
            #pragma unroll
            for (int bf = 0; bf < 2; bf++) {
                uint32_t r = wn * 32 + bf * 16 + bN;
                uint32_t off = (r * PADK + ks * 16 + bKof) * 2;
                ldsm4(bh[bf], smb + OFF_BH * 2 + off);
                ldsm4(bl[bf], smb + OFF_BL * 2 + off);
            }
            #pragma unroll
            for (int mf = 0; mf < 2; mf++)
                #pragma unroll
                for (int bf = 0; bf < 2; bf++) {
                    mma_bf16(acc[mf][bf * 2 + 0], ah[mf], bh[bf][0], bh[bf][1]);
                    mma_bf16(acc[mf][bf * 2 + 1], ah[mf], bh[bf][2], bh[bf][3]);
                    mma_bf16(acc[mf][bf * 2 + 0], ah[mf], bl[bf][0], bl[bf][1]);
                    mma_bf16(acc[mf][bf * 2 + 1], ah[mf], bl[bf][2], bl[bf][3]);
                    mma_bf16(acc[mf][bf * 2 + 0], al[mf], bh[bf][0], bh[bf][1]);
                    mma_bf16(acc[mf][bf * 2 + 1], al[mf], bh[bf][2], bh[bf][3]);
                }
        }
    }

    // --- epilogue: scatter directly from fragments
    if (mode == 0) {
        int t = bn0 >> 8;
        #pragma unroll
        for (int mf = 0; mf < 2; mf++)
            #pragma unroll
            for (int f = 0; f < 4; f++) {
                int bf = f >> 1, half = f & 1;
                #pragma unroll
                for (int e = 0; e < 4; e++) {
                    int rr = bm + wm * 32 + mf * 16 + (lane >> 2) + (e >> 1) * 8;
                    int cc = bn0 + wn * 32 + bf * 16 + half * 8 + (lane & 3) * 2 + (e & 1);
                    int s = rr >> 8, l = rr & 255;
                    int jj = cc & 255;
                    int h = jj >> 5, ch = jj & 31;
                    size_t dst = (((size_t)(s * H_ + h) * L_) + l) * C_ + ch;
                    float v = acc[mf][f][e];
                    if (t == 0)      g_q[dst] = v * QSCALE;
                    else if (t == 1) g_k[dst] = v;
                    else if (t == 2) g_v[dst] = v;
                    else             g_g[dst] = 1.f / (1.f + fast_exp2(-(v + bias[jj]) * LOG2E));
                }
            }
    } else {
        #pragma unroll
        for (int mf = 0; mf < 2; mf++)
            #pragma unroll
            for (int f = 0; f < 4; f++) {
                int bf = f >> 1, half = f & 1;
                #pragma unroll
                for (int e = 0; e < 4; e++) {
                    int rr = bm + wm * 32 + mf * 16 + (lane >> 2) + (e >> 1) * 8;
                    int cc = bn0 + wn * 32 + bf * 16 + half * 8 + (lane & 3) * 2 + (e & 1);
                    outp[(size_t)rr * D_ + cc] = acc[mf][f][e] + bias[cc];
                }
            }
    }
}

// ---------------- Attention: one block per (s,h), max-free softmax ---------
// float4 smem loads: 16 LDS.128 per key instead of 64 scalar LDS.
__global__ __launch_bounds__(256) void attn_kernel() {
    extern __shared__ float smem[];
    float* ks = smem;
    float* vs = smem + L_ * C_;
    float* bcol = smem + 2 * L_ * C_;
    int sh = blockIdx.x;
    int s = sh >> 3, h = sh & 7;
    size_t base = (size_t)sh * (L_ * C_);
    int tid = threadIdx.x;

    for (int i = tid; i < L_ * C_ / 4; i += 256) {
        ((float4*)ks)[i] = ((const float4*)(g_k + base))[i];
        ((float4*)vs)[i] = ((const float4*)(g_v + base))[i];
    }
    bcol[tid] = (g_rp[tid] != 0.f) ? NEG_BIAS2 : 0.f;
    __syncthreads();

    int l = tid;
    float4 q4[8];
    const float4* qsrc = (const float4*)(g_q + base + (size_t)l * C_);
    #pragma unroll
    for (int c = 0; c < 8; c++) q4[c] = qsrc[c];
    bool rowm = (g_sp[l] != 0.f);

    float ssum = 0.f;
    float4 acc[8];
    #pragma unroll
    for (int c = 0; c < 8; c++) acc[c] = make_float4(0.f, 0.f, 0.f, 0.f);

    for (int j = 0; j < L_; j++) {
        const float4* kr = (const float4*)(ks + j * C_);
        float s0 = 0.f, s1 = 0.f, s2 = 0.f, s3 = 0.f;
        #pragma unroll
        for (int c = 0; c < 8; c++) {
            float4 kv = kr[c];
            s0 = fmaf(q4[c].x, kv.x, s0);
            s1 = fmaf(q4[c].y, kv.y, s1);
            s2 = fmaf(q4[c].z, kv.z, s2);
            s3 = fmaf(q4[c].w, kv.w, s3);
        }
        float sc = (s0 + s1) + (s2 + s3);
        if (!rowm) sc += bcol[j];
        float p = fast_exp2(sc);
        ssum += p;
        const float4* vr = (const float4*)(vs + j * C_);
        #pragma unroll
        for (int c = 0; c < 8; c++) {
            float4 vv = vr[c];
            acc[c].x = fmaf(p, vv.x, acc[c].x);
            acc[c].y = fmaf(p, vv.y, acc[c].y);
            acc[c].z = fmaf(p, vv.z, acc[c].z);
            acc[c].w = fmaf(p, vv.w, acc[c].w);
        }
    }

    float inv = 1.f / ssum;
    size_t obase = ((size_t)(s * L_ + l)) * D_ + h * C_;
    size_t gbase = base + (size_t)l * C_;
    #pragma unroll
    for (int c = 0; c < 8; c++) {
        float o[4] = {acc[c].x, acc[c].y, acc[c].z, acc[c].w};
        #pragma unroll
        for (int e = 0; e < 4; e++) {
            float ov = o[e] * inv * g_g[gbase + c * 4 + e];
            __nv_bfloat16 hi = __float2bfloat16(ov);
            __nv_bfloat16 lo = __float2bfloat16(ov - __bfloat162float(hi));
            g_oh[obase + c * 4 + e] = hi;
            g_ol[obase + c * 4 + e] = lo;
        }
    }
}

// ---------------- launch ---------------------------------------------------
extern "C" void kernel_launch(void* const* d_in, const int* in_sizes, int n_in,
                              void* d_out, int out_size) {
    const float* m    = (const float*)d_in[0];
    const void*  spad = d_in[1];
    const void*  rpad = d_in[2];
    const float* ln_g = (const float*)d_in[3];
    const float* ln_b = (const float*)d_in[4];
    const float* Wq   = (const float*)d_in[5];
    const float* Wk   = (const float*)d_in[6];
    const float* Wv   = (const float*)d_in[7];
    const float* Wg   = (const float*)d_in[8];
    const float* bg   = (const float*)d_in[9];
    const float* Wo   = (const float*)d_in[10];
    const float* bo   = (const float*)d_in[11];
    float* out = (float*)d_out;

    static int smem_set = 0;
    if (!smem_set) {
        cudaFuncSetAttribute(gemm_kernel, cudaFuncAttributeMaxDynamicSharedMemorySize,
                             SM_GEMM_HALVES * 2);
        cudaFuncSetAttribute(attn_kernel, cudaFuncAttributeMaxDynamicSharedMemorySize,
                             (2 * L_ * C_ + L_) * (int)sizeof(float));
        smem_set = 1;
    }

    prep_mask_kernel<<<1, 256>>>(spad, rpad);
    prep_w_kernel<<<5 * 256, 256>>>(Wq, Wk, Wv, Wg, Wo);
    ln_kernel<<<MROWS / 8, 256>>>(m, ln_g, ln_b);

    __nv_bfloat16 *mh, *ml, *wh, *wl, *oh, *ol;
    cudaGetSymbolAddress((void**)&mh, g_mnh);
    cudaGetSymbolAddress((void**)&ml, g_mnl);
    cudaGetSymbolAddress((void**)&wh, g_wh);
    cudaGetSymbolAddress((void**)&wl, g_wl);
    cudaGetSymbolAddress((void**)&oh, g_oh);
    cudaGetSymbolAddress((void**)&ol, g_ol);

    dim3 gp(16, MROWS / 128);   // proj: N = [Wq|Wk|Wv|Wg]
    gemm_kernel<<<gp, 256, SM_GEMM_HALVES * 2>>>(mh, ml, wh, wl, bg, nullptr, 0);

    int attn_smem = (2 * L_ * C_ + L_) * (int)sizeof(float);
    attn_kernel<<<S_ * H_, 256, attn_smem>>>();

    dim3 go(4, MROWS / 128);    // out projection
    gemm_kernel<<<go, 256, SM_GEMM_HALVES * 2>>>(oh, ol, wh + 4 * D_ * D_,
                                                 wl + 4 * D_ * D_, bo, out, 1);
}

// round 15
// speedup vs baseline: 1.0367x; 1.0367x over previous
#include <cuda_runtime.h>
#include <cuda_bf16.h>
#include <cstdint>

// Problem dims (fixed): B=1, S=128, L=256, D=256, H=8, C=32
#define S_ 128
#define L_ 256
#define D_ 256
#define H_ 8
#define C_ 32
#define MROWS (S_ * L_)          // 32768
#define LOG2E 1.4426950408889634f
#define NEG_BIAS2 (-10000.0f * LOG2E)
#define QSCALE (0.17677669529663687f * LOG2E)  // (1/sqrt(32)) * log2(e)

// ---------------- scratch (device globals; no cudaMalloc allowed) ----------
__device__ __nv_bfloat16 g_mnh[MROWS * D_];
__device__ __nv_bfloat16 g_mnl[MROWS * D_];
__device__ __nv_bfloat16 g_wh[5 * D_ * D_];   // [Wq|Wk|Wv|Wg|Wo] hi
__device__ __nv_bfloat16 g_wl[5 * D_ * D_];   // lo
__device__ float g_q[MROWS * D_];    // [s][h][l][c], pre-scaled by QSCALE
__device__ float g_k[MROWS * D_];
__device__ float g_v[MROWS * D_];
__device__ float g_g[MROWS * D_];
__device__ __nv_bfloat16 g_oh[MROWS * D_];    // attn out hi, [s][l][h*32+c]
__device__ __nv_bfloat16 g_ol[MROWS * D_];
__device__ float g_sp[L_];
__device__ float g_rp[L_];

__device__ __forceinline__ float fast_exp2(float x) {
    float y;
    asm("ex2.approx.ftz.f32 %0, %1;" : "=f"(y) : "f"(x));
    return y;
}
__device__ __forceinline__ uint32_t smem_u32(const void* p) {
    uint32_t a;
    asm("{ .reg .u64 t; cvta.to.shared.u64 t, %1; cvt.u32.u64 %0, t; }" : "=r"(a) : "l"(p));
    return a;
}
__device__ __forceinline__ void ldsm4(uint32_t* r, uint32_t addr) {
    asm volatile("ldmatrix.sync.aligned.m8n8.x4.shared.b16 {%0,%1,%2,%3}, [%4];"
                 : "=r"(r[0]), "=r"(r[1]), "=r"(r[2]), "=r"(r[3]) : "r"(addr));
}
__device__ __forceinline__ void mma_bf16(float* c, const uint32_t* a, uint32_t b0,
                                         uint32_t b1) {
    asm volatile(
        "mma.sync.aligned.m16n8k16.row.col.f32.bf16.bf16.f32 "
        "{%0,%1,%2,%3}, {%4,%5,%6,%7}, {%8,%9}, {%0,%1,%2,%3};"
        : "+f"(c[0]), "+f"(c[1]), "+f"(c[2]), "+f"(c[3])
        : "r"(a[0]), "r"(a[1]), "r"(a[2]), "r"(a[3]), "r"(b0), "r"(b1));
}
__device__ __forceinline__ void cp16(uint32_t smaddr, const void* gptr) {
    asm volatile("cp.async.cg.shared.global [%0], [%1], 16;" :: "r"(smaddr), "l"(gptr));
}
#define CP_COMMIT() asm volatile("cp.async.commit_group;" ::: "memory")
#define CP_WAIT0()  asm volatile("cp.async.wait_group 0;" ::: "memory")

// ---------------- mask prep: dtype-agnostic (bool8 / int32 / float32) ------
__global__ void prep_mask_kernel(const void* sp_raw, const void* rp_raw) {
    __shared__ int flagF, flagOff;
    int tid = threadIdx.x;  // 256
    if (tid == 0) { flagF = 0; flagOff = 0; }
    __syncthreads();
    const unsigned char* pb = (const unsigned char*)sp_raw;
    const unsigned char* qb = (const unsigned char*)rp_raw;
    unsigned char b1 = pb[tid], b2 = qb[tid];
    if ((tid & 3) == 3 && (b1 == 0x3F || b2 == 0x3F)) atomicOr(&flagF, 1);
    if ((tid & 3) != 0 && (b1 != 0 || b2 != 0)) atomicOr(&flagOff, 1);
    __syncthreads();
    int mode = flagF ? 2 : (flagOff ? 0 : 1);
    float vs, vr;
    if (mode == 0) {
        vs = (((const unsigned char*)sp_raw)[tid] != 0) ? 1.f : 0.f;
        vr = (((const unsigned char*)rp_raw)[tid] != 0) ? 1.f : 0.f;
    } else if (mode == 1) {
        vs = (((const int*)sp_raw)[tid] != 0) ? 1.f : 0.f;
        vr = (((const int*)rp_raw)[tid] != 0) ? 1.f : 0.f;
    } else {
        vs = (((const float*)sp_raw)[tid] != 0.f) ? 1.f : 0.f;
        vr = (((const float*)rp_raw)[tid] != 0.f) ? 1.f : 0.f;
    }
    g_sp[tid] = vs;
    g_rp[tid] = vr;
}

// ---------------- weight prep: fp32 -> bf16 hi/lo --------------------------
__global__ __launch_bounds__(256) void prep_w_kernel(
    const float* __restrict__ Wq, const float* __restrict__ Wk,
    const float* __restrict__ Wv, const float* __restrict__ Wg,
    const float* __restrict__ Wo) {
    int row = blockIdx.x;      // 0..1279
    int tid = threadIdx.x;
    int t = row >> 8;
    const float* W = (t == 0) ? Wq : (t == 1) ? Wk : (t == 2) ? Wv : (t == 3) ? Wg : Wo;
    float v = W[(size_t)(row & 255) * D_ + tid];
    __nv_bfloat16 hi = __float2bfloat16(v);
    __nv_bfloat16 lo = __float2bfloat16(v - __bfloat162float(hi));
    g_wh[(size_t)row * D_ + tid] = hi;
    g_wl[(size_t)row * D_ + tid] = lo;
}

// ---------------- LayerNorm: warp per row -> bf16 hi/lo --------------------
__global__ __launch_bounds__(256) void ln_kernel(const float* __restrict__ m,
                                                 const float* __restrict__ gam,
                                                 const float* __restrict__ bet) {
    int row = blockIdx.x * 8 + (threadIdx.x >> 5);
    int lane = threadIdx.x & 31;
    const float4* src = (const float4*)(m + (size_t)row * D_);
    float4 a = src[lane], b = src[lane + 32];
    float s1 = a.x + a.y + a.z + a.w + b.x + b.y + b.z + b.w;
    float s2 = a.x * a.x + a.y * a.y + a.z * a.z + a.w * a.w +
               b.x * b.x + b.y * b.y + b.z * b.z + b.w * b.w;
    #pragma unroll
    for (int o = 16; o > 0; o >>= 1) {
        s1 += __shfl_xor_sync(0xFFFFFFFFu, s1, o);
        s2 += __shfl_xor_sync(0xFFFFFFFFu, s2, o);
    }
    float mu = s1 * (1.f / D_);
    float rstd = rsqrtf(s2 * (1.f / D_) - mu * mu + 1e-5f);
    float va[8] = {a.x, a.y, a.z, a.w, b.x, b.y, b.z, b.w};
    #pragma unroll
    for (int i = 0; i < 8; i++) {
        int c = (i < 4) ? (lane * 4 + i) : (128 + lane * 4 + i - 4);
        float y = (va[i] - mu) * rstd * gam[c] + bet[c];
        __nv_bfloat16 hi = __float2bfloat16(y);
        __nv_bfloat16 lo = __float2bfloat16(y - __bfloat162float(hi));
        g_mnh[(size_t)row * D_ + c] = hi;
        g_mnl[(size_t)row * D_ + c] = lo;
    }
}

// ---------------- mma.sync GEMM: C[128x64] = A[128x256] * B[64x256]^T ------
// bf16x3: hi*hi + hi*lo + lo*hi, fp32 accumulators. Fragments loaded ONCE per
// k16 step, all 3 passes run from registers. Warps tiled 4m x 2n (32x32 each).
// 2 CTAs/SM via __launch_bounds__(256,2); cp.async.cg smem fills.
#define PADK 72
#define OFF_AH 0
#define OFF_AL (128 * PADK)
#define OFF_BH (2 * 128 * PADK)
#define OFF_BL (2 * 128 * PADK + 64 * PADK)
#define SM_GEMM_HALVES (2 * 128 * PADK + 2 * 64 * PADK)   // 27648 halves = 55296 B

__global__ __launch_bounds__(256, 2) void gemm_kernel(
    const __nv_bfloat16* __restrict__ Ah, const __nv_bfloat16* __restrict__ Al,
    const __nv_bfloat16* __restrict__ Bh, const __nv_bfloat16* __restrict__ Bl,
    const float* __restrict__ bias, float* __restrict__ outp, int mode) {
    extern __shared__ __align__(16) __nv_bfloat16 sm[];
    uint32_t smb = smem_u32(sm);
    int tid = threadIdx.x;
    int wid = tid >> 5, lane = tid & 31;
    int wm = wid & 3, wn = wid >> 2;
    int bm = blockIdx.y * 128;
    int bn0 = blockIdx.x * 64;

    const __nv_bfloat16* A0 = Ah + (size_t)bm * D_;
    const __nv_bfloat16* A1 = Al + (size_t)bm * D_;
    const __nv_bfloat16* B0 = Bh + (size_t)bn0 * D_;
    const __nv_bfloat16* B1 = Bl + (size_t)bn0 * D_;

    float acc[2][4][4];
    #pragma unroll
    for (int i = 0; i < 2; i++)
        #pragma unroll
        for (int f = 0; f < 4; f++)
            #pragma unroll
            for (int e = 0; e < 4; e++) acc[i][f][e] = 0.f;

    uint32_t aKof = (lane >> 4) * 8;
    uint32_t bN = (lane & 7) + ((lane >> 4) << 3);
    uint32_t bKof = ((lane >> 3) & 1) * 8;

    for (int k0 = 0; k0 < D_; k0 += 64) {
        if (k0) __syncthreads();   // prior chunk's reads done before overwrite
        // fill: A 128x64 hi+lo (1024 x 16B each), B 64x64 hi+lo (512 each)
        #pragma unroll
        for (int t = 0; t < 4; t++) {
            int i = tid + t * 256;
            int r = i >> 3, sg = i & 7;
            uint32_t d = smb + (uint32_t)(r * PADK + sg * 8) * 2;
            const __nv_bfloat16* s = A0 + (size_t)r * D_ + k0 + sg * 8;
            cp16(d + OFF_AH * 2, s);
            cp16(d + OFF_AL * 2, A1 + (s - A0));
        }
        #pragma unroll
        for (int t = 0; t < 2; t++) {
            int i = tid + t * 256;
            int r = i >> 3, sg = i & 7;
            uint32_t d = smb + (uint32_t)(r * PADK + sg * 8) * 2;
            const __nv_bfloat16* s = B0 + (size_t)r * D_ + k0 + sg * 8;
            cp16(d + OFF_BH * 2, s);
            cp16(d + OFF_BL * 2, B1 + (s - B0));
        }
        CP_COMMIT();
        CP_WAIT0();
        __syncthreads();

        #pragma unroll
        for (int ks = 0; ks < 4; ks++) {
            uint32_t ah[2][4], al[2][4], bh[2][4], bl[2][4];
            #pragma unroll
            for (int mf = 0; mf < 2; mf++) {
                uint32_t r = wm * 32 + mf * 16 + (lane & 15);
                uint32_t off = (r * PADK + ks * 16 + aKof) * 2;
                ldsm4(ah[mf], smb + OFF_AH * 2 + off);
                ldsm4(al[mf], smb + OFF_AL * 2 + off);
            }
            #pragma unroll
            for (int bf = 0; bf < 2; bf++) {
                uint32_t r = wn * 32 + bf * 16 + bN;
                uint32_t off = (r * PADK + ks * 16 + bKof) * 2;
                ldsm4(bh[bf], smb + OFF_BH * 2 + off);
                ldsm4(bl[bf], smb + OFF_BL * 2 + off);
            }
            #pragma unroll
            for (int mf = 0; mf < 2; mf++)
                #pragma unroll
                for (int bf = 0; bf < 2; bf++) {
                    mma_bf16(acc[mf][bf * 2 + 0], ah[mf], bh[bf][0], bh[bf][1]);
                    mma_bf16(acc[mf][bf * 2 + 1], ah[mf], bh[bf][2], bh[bf][3]);
                    mma_bf16(acc[mf][bf * 2 + 0], ah[mf], bl[bf][0], bl[bf][1]);
                    mma_bf16(acc[mf][bf * 2 + 1], ah[mf], bl[bf][2], bl[bf][3]);
                    mma_bf16(acc[mf][bf * 2 + 0], al[mf], bh[bf][0], bh[bf][1]);
                    mma_bf16(acc[mf][bf * 2 + 1], al[mf], bh[bf][2], bh[bf][3]);
                }
        }
    }

    // --- epilogue: scatter directly from fragments
    if (mode == 0) {
        int t = bn0 >> 8;
        #pragma unroll
        for (int mf = 0; mf < 2; mf++)
            #pragma unroll
            for (int f = 0; f < 4; f++) {
                int bf = f >> 1, half = f & 1;
                #pragma unroll
                for (int e = 0; e < 4; e++) {
                    int rr = bm + wm * 32 + mf * 16 + (lane >> 2) + (e >> 1) * 8;
                    int cc = bn0 + wn * 32 + bf * 16 + half * 8 + (lane & 3) * 2 + (e & 1);
                    int s = rr >> 8, l = rr & 255;
                    int jj = cc & 255;
                    int h = jj >> 5, ch = jj & 31;
                    size_t dst = (((size_t)(s * H_ + h) * L_) + l) * C_ + ch;
                    float v = acc[mf][f][e];
                    if (t == 0)      g_q[dst] = v * QSCALE;
                    else if (t == 1) g_k[dst] = v;
                    else if (t == 2) g_v[dst] = v;
                    else             g_g[dst] = 1.f / (1.f + fast_exp2(-(v + bias[jj]) * LOG2E));
                }
            }
    } else {
        #pragma unroll
        for (int mf = 0; mf < 2; mf++)
            #pragma unroll
            for (int f = 0; f < 4; f++) {
                int bf = f >> 1, half = f & 1;
                #pragma unroll
                for (int e = 0; e < 4; e++) {
                    int rr = bm + wm * 32 + mf * 16 + (lane >> 2) + (e >> 1) * 8;
                    int cc = bn0 + wn * 32 + bf * 16 + half * 8 + (lane & 3) * 2 + (e & 1);
                    outp[(size_t)rr * D_ + cc] = acc[mf][f][e] + bias[cc];
                }
            }
    }
}

// ---------------- Attention: one block per (s,h), max-free softmax ---------
// float4 smem loads: 16 LDS.128 per key instead of 64 scalar LDS.
__global__ __launch_bounds__(256) void attn_kernel() {
    extern __shared__ float smem[];
    float* ks = smem;
    float* vs = smem + L_ * C_;
    float* bcol = smem + 2 * L_ * C_;
    int sh = blockIdx.x;
    int s = sh >> 3, h = sh & 7;
    size_t base = (size_t)sh * (L_ * C_);
    int tid = threadIdx.x;

    for (int i = tid; i < L_ * C_ / 4; i += 256) {
        ((float4*)ks)[i] = ((const float4*)(g_k + base))[i];
        ((float4*)vs)[i] = ((const float4*)(g_v + base))[i];
    }
    bcol[tid] = (g_rp[tid] != 0.f) ? NEG_BIAS2 : 0.f;
    __syncthreads();

    int l = tid;
    float4 q4[8];
    const float4* qsrc = (const float4*)(g_q + base + (size_t)l * C_);
    #pragma unroll
    for (int c = 0; c < 8; c++) q4[c] = qsrc[c];
    bool rowm = (g_sp[l] != 0.f);

    float ssum = 0.f;
    float4 acc[8];
    #pragma unroll
    for (int c = 0; c < 8; c++) acc[c] = make_float4(0.f, 0.f, 0.f, 0.f);

    for (int j = 0; j < L_; j++) {
        const float4* kr = (const float4*)(ks + j * C_);
        float s0 = 0.f, s1 = 0.f, s2 = 0.f, s3 = 0.f;
        #pragma unroll
        for (int c = 0; c < 8; c++) {
            float4 kv = kr[c];
            s0 = fmaf(q4[c].x, kv.x, s0);
            s1 = fmaf(q4[c].y, kv.y, s1);
            s2 = fmaf(q4[c].z, kv.z, s2);
            s3 = fmaf(q4[c].w, kv.w, s3);
        }
        float sc = (s0 + s1) + (s2 + s3);
        if (!rowm) sc += bcol[j];
        float p = fast_exp2(sc);
        ssum += p;
        const float4* vr = (const float4*)(vs + j * C_);
        #pragma unroll
        for (int c = 0; c < 8; c++) {
            float4 vv = vr[c];
            acc[c].x = fmaf(p, vv.x, acc[c].x);
            acc[c].y = fmaf(p, vv.y, acc[c].y);
            acc[c].z = fmaf(p, vv.z, acc[c].z);
            acc[c].w = fmaf(p, vv.w, acc[c].w);
        }
    }

    float inv = 1.f / ssum;
    size_t obase = ((size_t)(s * L_ + l)) * D_ + h * C_;
    size_t gbase = base + (size_t)l * C_;
    #pragma unroll
    for (int c = 0; c < 8; c++) {
        float o[4] = {acc[c].x, acc[c].y, acc[c].z, acc[c].w};
        #pragma unroll
        for (int e = 0; e < 4; e++) {
            float ov = o[e] * inv * g_g[gbase + c * 4 + e];
            __nv_bfloat16 hi = __float2bfloat16(ov);
            __nv_bfloat16 lo = __float2bfloat16(ov - __bfloat162float(hi));
            g_oh[obase + c * 4 + e] = hi;
            g_ol[obase + c * 4 + e] = lo;
        }
    }
}

// ---------------- launch ---------------------------------------------------
extern "C" void kernel_launch(void* const* d_in, const int* in_sizes, int n_in,
                              void* d_out, int out_size) {
    const float* m    = (const float*)d_in[0];
    const void*  spad = d_in[1];
    const void*  rpad = d_in[2];
    const float* ln_g = (const float*)d_in[3];
    const float* ln_b = (const float*)d_in[4];
    const float* Wq   = (const float*)d_in[5];
    const float* Wk   = (const float*)d_in[6];
    const float* Wv   = (const float*)d_in[7];
    const float* Wg   = (const float*)d_in[8];
    const float* bg   = (const float*)d_in[9];
    const float* Wo   = (const float*)d_in[10];
    const float* bo   = (const float*)d_in[11];
    float* out = (float*)d_out;

    static int smem_set = 0;
    if (!smem_set) {
        cudaFuncSetAttribute(gemm_kernel, cudaFuncAttributeMaxDynamicSharedMemorySize,
                             SM_GEMM_HALVES * 2);
        cudaFuncSetAttribute(attn_kernel, cudaFuncAttributeMaxDynamicSharedMemorySize,
                             (2 * L_ * C_ + L_) * (int)sizeof(float));
        smem_set = 1;
    }

    prep_mask_kernel<<<1, 256>>>(spad, rpad);
    prep_w_kernel<<<5 * 256, 256>>>(Wq, Wk, Wv, Wg, Wo);
    ln_kernel<<<MROWS / 8, 256>>>(m, ln_g, ln_b);

    __nv_bfloat16 *mh, *ml, *wh, *wl, *oh, *ol;
    cudaGetSymbolAddress((void**)&mh, g_mnh);
    cudaGetSymbolAddress((void**)&ml, g_mnl);
    cudaGetSymbolAddress((void**)&wh, g_wh);
    cudaGetSymbolAddress((void**)&wl, g_wl);
    cudaGetSymbolAddress((void**)&oh, g_oh);
    cudaGetSymbolAddress((void**)&ol, g_ol);

    dim3 gp(16, MROWS / 128);   // proj: N = [Wq|Wk|Wv|Wg]
    gemm_kernel<<<gp, 256, SM_GEMM_HALVES * 2>>>(mh, ml, wh, wl, bg, nullptr, 0);

    int attn_smem = (2 * L_ * C_ + L_) * (int)sizeof(float);
    attn_kernel<<<S_ * H_, 256, attn_smem>>>();

    dim3 go(4, MROWS / 128);    // out projection
    gemm_kernel<<<go, 256, SM_GEMM_HALVES * 2>>>(oh, ol, wh + 4 * D_ * D_,
                                                 wl + 4 * D_ * D_, bo, out, 1);
}

// round 16
// speedup vs baseline: 1.9110x; 1.8434x over previous
#include <cuda_runtime.h>
#include <cuda_bf16.h>
#include <cstdint>

// Problem dims (fixed): B=1, S=128, L=256, D=256, H=8, C=32
#define S_ 128
#define L_ 256
#define D_ 256
#define H_ 8
#define C_ 32
#define MROWS (S_ * L_)          // 32768
#define LOG2E 1.4426950408889634f
#define NEG_BIAS2 (-10000.0f * LOG2E)
#define QSCALE (0.17677669529663687f * LOG2E)  // (1/sqrt(32)) * log2(e)

// ---------------- scratch (device globals; no cudaMalloc allowed) ----------
__device__ __nv_bfloat16 g_mnh[MROWS * D_];
__device__ __nv_bfloat16 g_mnl[MROWS * D_];
__device__ __nv_bfloat16 g_wh[5 * D_ * D_];   // [Wq|Wk|Wv|Wg|Wo] hi
__device__ __nv_bfloat16 g_wl[5 * D_ * D_];   // lo
__device__ __nv_bfloat16 g_qh[MROWS * D_];    // [s][h][l][c], pre-scaled, hi
__device__ __nv_bfloat16 g_ql[MROWS * D_];
__device__ __nv_bfloat16 g_kh[MROWS * D_];    // [s][h][l][c]
__device__ __nv_bfloat16 g_kl[MROWS * D_];
__device__ __nv_bfloat16 g_vth[MROWS * D_];   // TRANSPOSED [s][h][c][l]
__device__ __nv_bfloat16 g_vtl[MROWS * D_];
__device__ float g_g[MROWS * D_];             // gate fp32 [s][h][l][c]
__device__ __nv_bfloat16 g_oh[MROWS * D_];    // attn out hi, [s][l][h*32+c]
__device__ __nv_bfloat16 g_ol[MROWS * D_];
__device__ float g_sp[L_];
__device__ float g_rp[L_];

__device__ __forceinline__ float fast_exp2(float x) {
    float y;
    asm("ex2.approx.ftz.f32 %0, %1;" : "=f"(y) : "f"(x));
    return y;
}
__device__ __forceinline__ uint32_t smem_u32(const void* p) {
    uint32_t a;
    asm("{ .reg .u64 t; cvta.to.shared.u64 t, %1; cvt.u32.u64 %0, t; }" : "=r"(a) : "l"(p));
    return a;
}
__device__ __forceinline__ void ldsm4(uint32_t* r, uint32_t addr) {
    asm volatile("ldmatrix.sync.aligned.m8n8.x4.shared.b16 {%0,%1,%2,%3}, [%4];"
                 : "=r"(r[0]), "=r"(r[1]), "=r"(r[2]), "=r"(r[3]) : "r"(addr));
}
__device__ __forceinline__ void mma_bf16(float* c, const uint32_t* a, uint32_t b0,
                                         uint32_t b1) {
    asm volatile(
        "mma.sync.aligned.m16n8k16.row.col.f32.bf16.bf16.f32 "
        "{%0,%1,%2,%3}, {%4,%5,%6,%7}, {%8,%9}, {%0,%1,%2,%3};"
        : "+f"(c[0]), "+f"(c[1]), "+f"(c[2]), "+f"(c[3])
        : "r"(a[0]), "r"(a[1]), "r"(a[2]), "r"(a[3]), "r"(b0), "r"(b1));
}
__device__ __forceinline__ void cp16(uint32_t smaddr, const void* gptr) {
    asm volatile("cp.async.cg.shared.global [%0], [%1], 16;" :: "r"(smaddr), "l"(gptr));
}
#define CP_COMMIT() asm volatile("cp.async.commit_group;" ::: "memory")
#define CP_WAIT0()  asm volatile("cp.async.wait_group 0;" ::: "memory")

// pack two fp32 -> bf16x2: element0 (low 16 bits) = v0, element1 = v1
__device__ __forceinline__ uint32_t pack_bf16x2(float v0, float v1) {
    uint32_t d;
    asm("cvt.rn.bf16x2.f32 %0, %1, %2;" : "=r"(d) : "f"(v1), "f"(v0));
    return d;
}
__device__ __forceinline__ void split_store_pair(__nv_bfloat16* Ah, __nv_bfloat16* Al,
                                                 size_t idx, float v0, float v1) {
    float h0 = __bfloat162float(__float2bfloat16(v0));
    float h1 = __bfloat162float(__float2bfloat16(v1));
    *(uint32_t*)(Ah + idx) = pack_bf16x2(v0, v1);
    *(uint32_t*)(Al + idx) = pack_bf16x2(v0 - h0, v1 - h1);
}

// ---------------- mask prep: dtype-agnostic (bool8 / int32 / float32) ------
__global__ void prep_mask_kernel(const void* sp_raw, const void* rp_raw) {
    __shared__ int flagF, flagOff;
    int tid = threadIdx.x;  // 256
    if (tid == 0) { flagF = 0; flagOff = 0; }
    __syncthreads();
    const unsigned char* pb = (const unsigned char*)sp_raw;
    const unsigned char* qb = (const unsigned char*)rp_raw;
    unsigned char b1 = pb[tid], b2 = qb[tid];
    if ((tid & 3) == 3 && (b1 == 0x3F || b2 == 0x3F)) atomicOr(&flagF, 1);
    if ((tid & 3) != 0 && (b1 != 0 || b2 != 0)) atomicOr(&flagOff, 1);
    __syncthreads();
    int mode = flagF ? 2 : (flagOff ? 0 : 1);
    float vs, vr;
    if (mode == 0) {
        vs = (((const unsigned char*)sp_raw)[tid] != 0) ? 1.f : 0.f;
        vr = (((const unsigned char*)rp_raw)[tid] != 0) ? 1.f : 0.f;
    } else if (mode == 1) {
        vs = (((const int*)sp_raw)[tid] != 0) ? 1.f : 0.f;
        vr = (((const int*)rp_raw)[tid] != 0) ? 1.f : 0.f;
    } else {
        vs = (((const float*)sp_raw)[tid] != 0.f) ? 1.f : 0.f;
        vr = (((const float*)rp_raw)[tid] != 0.f) ? 1.f : 0.f;
    }
    g_sp[tid] = vs;
    g_rp[tid] = vr;
}

// ---------------- weight prep: fp32 -> bf16 hi/lo --------------------------
__global__ __launch_bounds__(256) void prep_w_kernel(
    const float* __restrict__ Wq, const float* __restrict__ Wk,
    const float* __restrict__ Wv, const float* __restrict__ Wg,
    const float* __restrict__ Wo) {
    int row = blockIdx.x;      // 0..1279
    int tid = threadIdx.x;
    int t = row >> 8;
    const float* W = (t == 0) ? Wq : (t == 1) ? Wk : (t == 2) ? Wv : (t == 3) ? Wg : Wo;
    float v = W[(size_t)(row & 255) * D_ + tid];
    __nv_bfloat16 hi = __float2bfloat16(v);
    __nv_bfloat16 lo = __float2bfloat16(v - __bfloat162float(hi));
    g_wh[(size_t)row * D_ + tid] = hi;
    g_wl[(size_t)row * D_ + tid] = lo;
}

// ---------------- LayerNorm: warp per row -> bf16 hi/lo --------------------
__global__ __launch_bounds__(256) void ln_kernel(const float* __restrict__ m,
                                                 const float* __restrict__ gam,
                                                 const float* __restrict__ bet) {
    int row = blockIdx.x * 8 + (threadIdx.x >> 5);
    int lane = threadIdx.x & 31;
    const float4* src = (const float4*)(m + (size_t)row * D_);
    float4 a = src[lane], b = src[lane + 32];
    float s1 = a.x + a.y + a.z + a.w + b.x + b.y + b.z + b.w;
    float s2 = a.x * a.x + a.y * a.y + a.z * a.z + a.w * a.w +
               b.x * b.x + b.y * b.y + b.z * b.z + b.w * b.w;
    #pragma unroll
    for (int o = 16; o > 0; o >>= 1) {
        s1 += __shfl_xor_sync(0xFFFFFFFFu, s1, o);
        s2 += __shfl_xor_sync(0xFFFFFFFFu, s2, o);
    }
    float mu = s1 * (1.f / D_);
    float rstd = rsqrtf(s2 * (1.f / D_) - mu * mu + 1e-5f);
    float va[8] = {a.x, a.y, a.z, a.w, b.x, b.y, b.z, b.w};
    #pragma unroll
    for (int i = 0; i < 8; i++) {
        int c = (i < 4) ? (lane * 4 + i) : (128 + lane * 4 + i - 4);
        float y = (va[i] - mu) * rstd * gam[c] + bet[c];
        __nv_bfloat16 hi = __float2bfloat16(y);
        __nv_bfloat16 lo = __float2bfloat16(y - __bfloat162float(hi));
        g_mnh[(size_t)row * D_ + c] = hi;
        g_mnl[(size_t)row * D_ + c] = lo;
    }
}

// ---------------- mma.sync GEMM: C[128x64] = A[128x256] * B[64x256]^T ------
#define PADK 72
#define OFF_AH 0
#define OFF_AL (128 * PADK)
#define OFF_BH (2 * 128 * PADK)
#define OFF_BL (2 * 128 * PADK + 64 * PADK)
#define SM_GEMM_HALVES (2 * 128 * PADK + 2 * 64 * PADK)   // 55296 B

__global__ __launch_bounds__(256, 2) void gemm_kernel(
    const __nv_bfloat16* __restrict__ Ah, const __nv_bfloat16* __restrict__ Al,
    const __nv_bfloat16* __restrict__ Bh, const __nv_bfloat16* __restrict__ Bl,
    const float* __restrict__ bias, float* __restrict__ outp, int mode) {
    extern __shared__ __align__(16) __nv_bfloat16 sm[];
    uint32_t smb = smem_u32(sm);
    int tid = threadIdx.x;
    int wid = tid >> 5, lane = tid & 31;
    int wm = wid & 3, wn = wid >> 2;
    int bm = blockIdx.y * 128;
    int bn0 = blockIdx.x * 64;

    const __nv_bfloat16* A0 = Ah + (size_t)bm * D_;
    const __nv_bfloat16* A1 = Al + (size_t)bm * D_;
    const __nv_bfloat16* B0 = Bh + (size_t)bn0 * D_;
    const __nv_bfloat16* B1 = Bl + (size_t)bn0 * D_;

    float acc[2][4][4];
    #pragma unroll
    for (int i = 0; i < 2; i++)
        #pragma unroll
        for (int f = 0; f < 4; f++)
            #pragma unroll
            for (int e = 0; e < 4; e++) acc[i][f][e] = 0.f;

    uint32_t aKof = (lane >> 4) * 8;
    uint32_t bN = (lane & 7) + ((lane >> 4) << 3);
    uint32_t bKof = ((lane >> 3) & 1) * 8;

    for (int k0 = 0; k0 < D_; k0 += 64) {
        if (k0) __syncthreads();
        #pragma unroll
        for (int t = 0; t < 4; t++) {
            int i = tid + t * 256;
            int r = i >> 3, sg = i & 7;
            uint32_t d = smb + (uint32_t)(r * PADK + sg * 8) * 2;
            const __nv_bfloat16* s = A0 + (size_t)r * D_ + k0 + sg * 8;
            cp16(d + OFF_AH * 2, s);
            cp16(d + OFF_AL * 2, A1 + (s - A0));
        }
        #pragma unroll
        for (int t = 0; t < 2; t++) {
            int i = tid + t * 256;
            int r = i >> 3, sg = i & 7;
            uint32_t d = smb + (uint32_t)(r * PADK + sg * 8) * 2;
            const __nv_bfloat16* s = B0 + (size_t)r * D_ + k0 + sg * 8;
            cp16(d + OFF_BH * 2, s);
            cp16(d + OFF_BL * 2, B1 + (s - B0));
        }
        CP_COMMIT();
        CP_WAIT0();
        __syncthreads();

        #pragma unroll
        for (int ks = 0; ks < 4; ks++) {
            uint32_t ah[2][4], al[2][4], bh[2][4], bl[2][4];
            #pragma unroll
            for (int mf = 0; mf < 2; mf++) {
                uint32_t r = wm * 32 + mf * 16 + (lane & 15);
                uint32_t off = (r * PADK + ks * 16 + aKof) * 2;
                ldsm4(ah[mf], smb + OFF_AH * 2 + off);
                ldsm4(al[mf], smb + OFF_AL * 2 + off);
            }
            #pragma unroll
            for (int bf = 0; bf < 2; bf++) {
                uint32_t r = wn * 32 + bf * 16 + bN;
                uint32_t off = (r * PADK + ks * 16 + bKof) * 2;
                ldsm4(bh[bf], smb + OFF_BH * 2 + off);
                ldsm4(bl[bf], smb + OFF_BL * 2 + off);
            }
            #pragma unroll
            for (int mf = 0; mf < 2; mf++)
                #pragma unroll
                for (int bf = 0; bf < 2; bf++) {
                    mma_bf16(acc[mf][bf * 2 + 0], ah[mf], bh[bf][0], bh[bf][1]);
                    mma_bf16(acc[mf][bf * 2 + 1], ah[mf], bh[bf][2], bh[bf][3]);
                    mma_bf16(acc[mf][bf * 2 + 0], ah[mf], bl[bf][0], bl[bf][1]);
                    mma_bf16(acc[mf][bf * 2 + 1], ah[mf], bl[bf][2], bl[bf][3]);
                    mma_bf16(acc[mf][bf * 2 + 0], al[mf], bh[bf][0], bh[bf][1]);
                    mma_bf16(acc[mf][bf * 2 + 1], al[mf], bh[bf][2], bh[bf][3]);
                }
        }
    }

    // --- epilogue
    if (mode == 0) {
        int t = bn0 >> 8;
        #pragma unroll
        for (int mf = 0; mf < 2; mf++)
            #pragma unroll
            for (int f = 0; f < 4; f++) {
                int bf = f >> 1, half = f & 1;
                int rr = bm + wm * 32 + mf * 16 + (lane >> 2);
                int cc = bn0 + wn * 32 + bf * 16 + half * 8 + (lane & 3) * 2;
                int jj = cc & 255;
                int hh = jj >> 5, ch = jj & 31;
                float v0 = acc[mf][f][0], v1 = acc[mf][f][1];   // row rr
                float v2 = acc[mf][f][2], v3 = acc[mf][f][3];   // row rr+8
                #pragma unroll
                for (int rp = 0; rp < 2; rp++) {
                    int rrow = rr + rp * 8;
                    int s = rrow >> 8, l = rrow & 255;
                    float a0 = rp ? v2 : v0, a1 = rp ? v3 : v1;
                    size_t shb = (size_t)(s * H_ + hh);
                    if (t == 0) {
                        split_store_pair(g_qh, g_ql, (shb * L_ + l) * C_ + ch,
                                         a0 * QSCALE, a1 * QSCALE);
                    } else if (t == 1) {
                        split_store_pair(g_kh, g_kl, (shb * L_ + l) * C_ + ch, a0, a1);
                    } else if (t == 2) {
                        size_t i0 = (shb * C_ + ch) * L_ + l;      // transposed
                        float h0 = __bfloat162float(__float2bfloat16(a0));
                        float h1 = __bfloat162float(__float2bfloat16(a1));
                        g_vth[i0] = __float2bfloat16(a0);
                        g_vtl[i0] = __float2bfloat16(a0 - h0);
                        g_vth[i0 + L_] = __float2bfloat16(a1);
                        g_vtl[i0 + L_] = __float2bfloat16(a1 - h1);
                    } else {
                        size_t i0 = (shb * L_ + l) * C_ + ch;
                        g_g[i0] = 1.f / (1.f + fast_exp2(-(a0 + bias[jj]) * LOG2E));
                        g_g[i0 + 1] = 1.f / (1.f + fast_exp2(-(a1 + bias[jj + 1]) * LOG2E));
                    }
                }
            }
    } else {
        #pragma unroll
        for (int mf = 0; mf < 2; mf++)
            #pragma unroll
            for (int f = 0; f < 4; f++) {
                int bf = f >> 1, half = f & 1;
                #pragma unroll
                for (int e = 0; e < 4; e++) {
                    int rr = bm + wm * 32 + mf * 16 + (lane >> 2) + (e >> 1) * 8;
                    int cc = bn0 + wn * 32 + bf * 16 + half * 8 + (lane & 3) * 2 + (e & 1);
                    outp[(size_t)rr * D_ + cc] = acc[mf][f][e] + bias[cc];
                }
            }
    }
}

// ---------------- Tensor-core attention: one block per (s,h) ---------------
// 512 thr, 16 warps x 16 q-rows. S = QK^T (bf16x3 mma), exp2 in regs,
// re-pack P into A-frags (C-layout == A-layout trick), O += P*V^T (bf16x3).
#define KPAD 40                        // halves per K row (32 + 8 pad)
#define VPAD 264                       // halves per Vt row (256 + 8 pad)
#define ATT_BCOL 0                     // float[256]            : 1024 B
#define ATT_KH  1024                   // bf16 [256][KPAD]      : 20480 B
#define ATT_KL  (ATT_KH + 20480)
#define ATT_VH  (ATT_KL + 20480)       // bf16 [32][VPAD]       : 16896 B
#define ATT_VL  (ATT_VH + 16896)
#define ATT_SMEM (ATT_VL + 16896)      // 75776 B

__global__ __launch_bounds__(512, 1) void attn_kernel() {
    extern __shared__ __align__(16) char asm_[];
    uint32_t smb = smem_u32(asm_);
    float* bc = (float*)(asm_ + ATT_BCOL);
    int sh = blockIdx.x;
    int s = sh >> 3, h = sh & 7;
    size_t base = (size_t)sh * (L_ * C_);
    int tid = threadIdx.x;
    int wid = tid >> 5, lane = tid & 31;

    // stage K hi/lo [256][32] -> [256][KPAD]
    for (int i = tid; i < 1024; i += 512) {
        int r = i >> 2, sg = (i & 3) * 8;
        uint32_t d = (uint32_t)(r * KPAD + sg) * 2;
        *(uint4*)(asm_ + ATT_KH + d) = *(const uint4*)(g_kh + base + r * 32 + sg);
        *(uint4*)(asm_ + ATT_KL + d) = *(const uint4*)(g_kl + base + r * 32 + sg);
    }
    // stage Vt hi/lo [32][256] -> [32][VPAD]
    for (int i = tid; i < 1024; i += 512) {
        int r = i >> 5, sg = (i & 31) * 8;
        uint32_t d = (uint32_t)(r * VPAD + sg) * 2;
        *(uint4*)(asm_ + ATT_VH + d) = *(const uint4*)(g_vth + base + r * 256 + sg);
        *(uint4*)(asm_ + ATT_VL + d) = *(const uint4*)(g_vtl + base + r * 256 + sg);
    }
    if (tid < 256) bc[tid] = (g_rp[tid] != 0.f) ? NEG_BIAS2 : 0.f;
    __syncthreads();

    int g4 = lane >> 2, t4 = lane & 3;
    int rowA = wid * 16 + g4;              // q rows rowA, rowA+8
    bool mA = (g_sp[rowA] != 0.f);
    bool mB = (g_sp[rowA + 8] != 0.f);

    // Q A-fragments via direct LDG (hi, lo), 2 k16 steps
    uint32_t qh[2][4], ql[2][4];
    {
        const __nv_bfloat16* q0 = g_qh + base + (size_t)rowA * 32;
        const __nv_bfloat16* q1 = g_ql + base + (size_t)rowA * 32;
        #pragma unroll
        for (int ks = 0; ks < 2; ks++) {
            int c0 = ks * 16 + 2 * t4;
            qh[ks][0] = *(const uint32_t*)(q0 + c0);
            qh[ks][1] = *(const uint32_t*)(q0 + 8 * 32 + c0);
            qh[ks][2] = *(const uint32_t*)(q0 + c0 + 8);
            qh[ks][3] = *(const uint32_t*)(q0 + 8 * 32 + c0 + 8);
            ql[ks][0] = *(const uint32_t*)(q1 + c0);
            ql[ks][1] = *(const uint32_t*)(q1 + 8 * 32 + c0);
            ql[ks][2] = *(const uint32_t*)(q1 + c0 + 8);
            ql[ks][3] = *(const uint32_t*)(q1 + 8 * 32 + c0 + 8);
        }
    }

    float o[4][4];
    #pragma unroll
    for (int f = 0; f < 4; f++)
        #pragma unroll
        for (int e = 0; e < 4; e++) o[f][e] = 0.f;
    float rs0 = 0.f, rs1 = 0.f;

    uint32_t bN = (lane & 7) + ((lane >> 4) << 3);
    uint32_t bKof = ((lane >> 3) & 1) * 8;

    #pragma unroll
    for (int chunk = 0; chunk < 4; chunk++) {
        int j0 = chunk * 64;
        float S[8][4];
        #pragma unroll
        for (int f = 0; f < 8; f++)
            #pragma unroll
            for (int e = 0; e < 4; e++) S[f][e] = 0.f;

        // S = Q K^T  (3-pass bf16)
        #pragma unroll
        for (int ks = 0; ks < 2; ks++)
            #pragma unroll
            for (int nf = 0; nf < 4; nf++) {
                uint32_t kh4[4], kl4[4];
                uint32_t addr = smb + ATT_KH +
                    ((uint32_t)(j0 + nf * 16 + bN) * KPAD + ks * 16 + bKof) * 2;
                ldsm4(kh4, addr);
                ldsm4(kl4, addr + 20480);
                mma_bf16(S[nf * 2 + 0], qh[ks], kh4[0], kh4[1]);
                mma_bf16(S[nf * 2 + 1], qh[ks], kh4[2], kh4[3]);
                mma_bf16(S[nf * 2 + 0], qh[ks], kl4[0], kl4[1]);
                mma_bf16(S[nf * 2 + 1], qh[ks], kl4[2], kl4[3]);
                mma_bf16(S[nf * 2 + 0], ql[ks], kh4[0], kh4[1]);
                mma_bf16(S[nf * 2 + 1], ql[ks], kh4[2], kh4[3]);
            }

        // bias + exp2 + pack into P A-frags (hi, lo)
        uint32_t ph[4][4], plo[4][4];
        #pragma unroll
        for (int f = 0; f < 8; f++) {
            int j = j0 + f * 8 + 2 * t4;
            float b0 = bc[j], b1 = bc[j + 1];
            float p0 = fast_exp2(S[f][0] + (mA ? 0.f : b0));
            float p1 = fast_exp2(S[f][1] + (mA ? 0.f : b1));
            float p2 = fast_exp2(S[f][2] + (mB ? 0.f : b0));
            float p3 = fast_exp2(S[f][3] + (mB ? 0.f : b1));
            rs0 += p0 + p1;
            rs1 += p2 + p3;
            float h0 = __bfloat162float(__float2bfloat16(p0));
            float h1 = __bfloat162float(__float2bfloat16(p1));
            float h2 = __bfloat162float(__float2bfloat16(p2));
            float h3 = __bfloat162float(__float2bfloat16(p3));
            int f2 = f >> 1, off = (f & 1) * 2;
            ph[f2][off + 0] = pack_bf16x2(p0, p1);
            ph[f2][off + 1] = pack_bf16x2(p2, p3);
            plo[f2][off + 0] = pack_bf16x2(p0 - h0, p1 - h1);
            plo[f2][off + 1] = pack_bf16x2(p2 - h2, p3 - h3);
        }

        // O += P * V^T  (3-pass: ph*vh + ph*vl + plo*vh)
        #pragma unroll
        for (int f2 = 0; f2 < 4; f2++)
            #pragma unroll
            for (int ng = 0; ng < 2; ng++) {
                uint32_t vh4[4], vl4[4];
                uint32_t vaddr = smb + ATT_VH +
                    ((uint32_t)(ng * 16 + bN) * VPAD + j0 + f2 * 16 + bKof) * 2;
                ldsm4(vh4, vaddr);
                ldsm4(vl4, vaddr + 16896);
                mma_bf16(o[ng * 2 + 0], ph[f2], vh4[0], vh4[1]);
                mma_bf16(o[ng * 2 + 1], ph[f2], vh4[2], vh4[3]);
                mma_bf16(o[ng * 2 + 0], ph[f2], vl4[0], vl4[1]);
                mma_bf16(o[ng * 2 + 1], ph[f2], vl4[2], vl4[3]);
                mma_bf16(o[ng * 2 + 0], plo[f2], vh4[0], vh4[1]);
                mma_bf16(o[ng * 2 + 1], plo[f2], vh4[2], vh4[3]);
            }
    }

    // row-sum reduce across the 4 lanes sharing each row
    rs0 += __shfl_xor_sync(0xFFFFFFFFu, rs0, 1);
    rs0 += __shfl_xor_sync(0xFFFFFFFFu, rs0, 2);
    rs1 += __shfl_xor_sync(0xFFFFFFFFu, rs1, 1);
    rs1 += __shfl_xor_sync(0xFFFFFFFFu, rs1, 2);
    float inv0 = 1.f / rs0, inv1 = 1.f / rs1;

    // epilogue: normalize, gate, split to bf16 hi/lo
    #pragma unroll
    for (int nf = 0; nf < 4; nf++) {
        int c = nf * 8 + 2 * t4;
        float2 ga = *(const float2*)(g_g + base + (size_t)rowA * 32 + c);
        float2 gb = *(const float2*)(g_g + base + (size_t)(rowA + 8) * 32 + c);
        float v0 = o[nf][0] * inv0 * ga.x;
        float v1 = o[nf][1] * inv0 * ga.y;
        float v2 = o[nf][2] * inv1 * gb.x;
        float v3 = o[nf][3] * inv1 * gb.y;
        size_t oA = ((size_t)(s * L_ + rowA)) * D_ + h * 32 + c;
        size_t oB = ((size_t)(s * L_ + rowA + 8)) * D_ + h * 32 + c;
        split_store_pair(g_oh, g_ol, oA, v0, v1);
        split_store_pair(g_oh, g_ol, oB, v2, v3);
    }
}

// ---------------- launch ---------------------------------------------------
extern "C" void kernel_launch(void* const* d_in, const int* in_sizes, int n_in,
                              void* d_out, int out_size) {
    const float* m    = (const float*)d_in[0];
    const void*  spad = d_in[1];
    const void*  rpad = d_in[2];
    const float* ln_g = (const float*)d_in[3];
    const float* ln_b = (const float*)d_in[4];
    const float* Wq   = (const float*)d_in[5];
    const float* Wk   = (const float*)d_in[6];
    const float* Wv   = (const float*)d_in[7];
    const float* Wg   = (const float*)d_in[8];
    const float* bg   = (const float*)d_in[9];
    const float* Wo   = (const float*)d_in[10];
    const float* bo   = (const float*)d_in[11];
    float* out = (float*)d_out;

    static int smem_set = 0;
    if (!smem_set) {
        cudaFuncSetAttribute(gemm_kernel, cudaFuncAttributeMaxDynamicSharedMemorySize,
                             SM_GEMM_HALVES * 2);
        cudaFuncSetAttribute(attn_kernel, cudaFuncAttributeMaxDynamicSharedMemorySize,
                             ATT_SMEM);
        smem_set = 1;
    }

    prep_mask_kernel<<<1, 256>>>(spad, rpad);
    prep_w_kernel<<<5 * 256, 256>>>(Wq, Wk, Wv, Wg, Wo);
    ln_kernel<<<MROWS / 8, 256>>>(m, ln_g, ln_b);

    __nv_bfloat16 *mh, *ml, *wh, *wl, *oh, *ol;
    cudaGetSymbolAddress((void**)&mh, g_mnh);
    cudaGetSymbolAddress((void**)&ml, g_mnl);
    cudaGetSymbolAddress((void**)&wh, g_wh);
    cudaGetSymbolAddress((void**)&wl, g_wl);
    cudaGetSymbolAddress((void**)&oh, g_oh);
    cudaGetSymbolAddress((void**)&ol, g_ol);

    dim3 gp(16, MROWS / 128);   // proj: N = [Wq|Wk|Wv|Wg]
    gemm_kernel<<<gp, 256, SM_GEMM_HALVES * 2>>>(mh, ml, wh, wl, bg, nullptr, 0);

    attn_kernel<<<S_ * H_, 512, ATT_SMEM>>>();

    dim3 go(4, MROWS / 128);    // out projection
    gemm_kernel<<<go, 256, SM_GEMM_HALVES * 2>>>(oh, ol, wh + 4 * D_ * D_,
                                                 wl + 4 * D_ * D_, bo, out, 1);
}

// round 17
// speedup vs baseline: 2.0869x; 1.0920x over previous
#include <cuda_runtime.h>
#include <cuda_bf16.h>
#include <cstdint>

// Problem dims (fixed): B=1, S=128, L=256, D=256, H=8, C=32
#define S_ 128
#define L_ 256
#define D_ 256
#define H_ 8
#define C_ 32
#define MROWS (S_ * L_)          // 32768
#define LOG2E 1.4426950408889634f
#define NEG_BIAS2 (-10000.0f * LOG2E)
#define QSCALE (0.17677669529663687f * LOG2E)  // (1/sqrt(32)) * log2(e)

// ---------------- scratch (device globals; no cudaMalloc allowed) ----------
__device__ __nv_bfloat16 g_mnh[MROWS * D_];
__device__ __nv_bfloat16 g_mnl[MROWS * D_];
__device__ __nv_bfloat16 g_wh[5 * D_ * D_];   // [Wq|Wk|Wv|Wg|Wo] hi
__device__ __nv_bfloat16 g_wl[5 * D_ * D_];   // lo
__device__ __nv_bfloat16 g_qh[MROWS * D_];    // [s][h][l][c], pre-scaled, hi
__device__ __nv_bfloat16 g_ql[MROWS * D_];
__device__ __nv_bfloat16 g_kh[MROWS * D_];    // [s][h][l][c]
__device__ __nv_bfloat16 g_kl[MROWS * D_];
__device__ __nv_bfloat16 g_vth[MROWS * D_];   // TRANSPOSED [s][h][c][l]
__device__ __nv_bfloat16 g_vtl[MROWS * D_];
__device__ float g_g[MROWS * D_];             // gate fp32 [s][h][l][c]
__device__ __nv_bfloat16 g_oh[MROWS * D_];    // attn out hi, [s][l][h*32+c]
__device__ __nv_bfloat16 g_ol[MROWS * D_];
__device__ float g_sp[L_];
__device__ float g_rp[L_];

__device__ __forceinline__ float fast_exp2(float x) {
    float y;
    asm("ex2.approx.ftz.f32 %0, %1;" : "=f"(y) : "f"(x));
    return y;
}
__device__ __forceinline__ uint32_t smem_u32(const void* p) {
    uint32_t a;
    asm("{ .reg .u64 t; cvta.to.shared.u64 t, %1; cvt.u32.u64 %0, t; }" : "=r"(a) : "l"(p));
    return a;
}
__device__ __forceinline__ void ldsm4(uint32_t* r, uint32_t addr) {
    asm volatile("ldmatrix.sync.aligned.m8n8.x4.shared.b16 {%0,%1,%2,%3}, [%4];"
                 : "=r"(r[0]), "=r"(r[1]), "=r"(r[2]), "=r"(r[3]) : "r"(addr));
}
__device__ __forceinline__ void mma_bf16(float* c, const uint32_t* a, uint32_t b0,
                                         uint32_t b1) {
    asm volatile(
        "mma.sync.aligned.m16n8k16.row.col.f32.bf16.bf16.f32 "
        "{%0,%1,%2,%3}, {%4,%5,%6,%7}, {%8,%9}, {%0,%1,%2,%3};"
        : "+f"(c[0]), "+f"(c[1]), "+f"(c[2]), "+f"(c[3])
        : "r"(a[0]), "r"(a[1]), "r"(a[2]), "r"(a[3]), "r"(b0), "r"(b1));
}
__device__ __forceinline__ void cp16(uint32_t smaddr, const void* gptr) {
    asm volatile("cp.async.cg.shared.global [%0], [%1], 16;" :: "r"(smaddr), "l"(gptr));
}
#define CP_COMMIT() asm volatile("cp.async.commit_group;" ::: "memory")
#define CP_WAIT0()  asm volatile("cp.async.wait_group 0;" ::: "memory")

// pack two fp32 -> bf16x2: element0 (low 16 bits) = v0, element1 = v1
__device__ __forceinline__ uint32_t pack_bf16x2(float v0, float v1) {
    uint32_t d;
    asm("cvt.rn.bf16x2.f32 %0, %1, %2;" : "=r"(d) : "f"(v1), "f"(v0));
    return d;
}
__device__ __forceinline__ void split_store_pair(__nv_bfloat16* Ah, __nv_bfloat16* Al,
                                                 size_t idx, float v0, float v1) {
    float h0 = __bfloat162float(__float2bfloat16(v0));
    float h1 = __bfloat162float(__float2bfloat16(v1));
    *(uint32_t*)(Ah + idx) = pack_bf16x2(v0, v1);
    *(uint32_t*)(Al + idx) = pack_bf16x2(v0 - h0, v1 - h1);
}

// ---------------- mask prep: dtype-agnostic (bool8 / int32 / float32) ------
__global__ void prep_mask_kernel(const void* sp_raw, const void* rp_raw) {
    __shared__ int flagF, flagOff;
    int tid = threadIdx.x;  // 256
    if (tid == 0) { flagF = 0; flagOff = 0; }
    __syncthreads();
    const unsigned char* pb = (const unsigned char*)sp_raw;
    const unsigned char* qb = (const unsigned char*)rp_raw;
    unsigned char b1 = pb[tid], b2 = qb[tid];
    if ((tid & 3) == 3 && (b1 == 0x3F || b2 == 0x3F)) atomicOr(&flagF, 1);
    if ((tid & 3) != 0 && (b1 != 0 || b2 != 0)) atomicOr(&flagOff, 1);
    __syncthreads();
    int mode = flagF ? 2 : (flagOff ? 0 : 1);
    float vs, vr;
    if (mode == 0) {
        vs = (((const unsigned char*)sp_raw)[tid] != 0) ? 1.f : 0.f;
        vr = (((const unsigned char*)rp_raw)[tid] != 0) ? 1.f : 0.f;
    } else if (mode == 1) {
        vs = (((const int*)sp_raw)[tid] != 0) ? 1.f : 0.f;
        vr = (((const int*)rp_raw)[tid] != 0) ? 1.f : 0.f;
    } else {
        vs = (((const float*)sp_raw)[tid] != 0.f) ? 1.f : 0.f;
        vr = (((const float*)rp_raw)[tid] != 0.f) ? 1.f : 0.f;
    }
    g_sp[tid] = vs;
    g_rp[tid] = vr;
}

// ---------------- weight prep: fp32 -> bf16 hi/lo --------------------------
__global__ __launch_bounds__(256) void prep_w_kernel(
    const float* __restrict__ Wq, const float* __restrict__ Wk,
    const float* __restrict__ Wv, const float* __restrict__ Wg,
    const float* __restrict__ Wo) {
    int row = blockIdx.x;      // 0..1279
    int tid = threadIdx.x;
    int t = row >> 8;
    const float* W = (t == 0) ? Wq : (t == 1) ? Wk : (t == 2) ? Wv : (t == 3) ? Wg : Wo;
    float v = W[(size_t)(row & 255) * D_ + tid];
    __nv_bfloat16 hi = __float2bfloat16(v);
    __nv_bfloat16 lo = __float2bfloat16(v - __bfloat162float(hi));
    g_wh[(size_t)row * D_ + tid] = hi;
    g_wl[(size_t)row * D_ + tid] = lo;
}

// ---------------- LayerNorm: warp per row -> bf16 hi/lo --------------------
__global__ __launch_bounds__(256) void ln_kernel(const float* __restrict__ m,
                                                 const float* __restrict__ gam,
                                                 const float* __restrict__ bet) {
    int row = blockIdx.x * 8 + (threadIdx.x >> 5);
    int lane = threadIdx.x & 31;
    const float4* src = (const float4*)(m + (size_t)row * D_);
    float4 a = src[lane], b = src[lane + 32];
    float s1 = a.x + a.y + a.z + a.w + b.x + b.y + b.z + b.w;
    float s2 = a.x * a.x + a.y * a.y + a.z * a.z + a.w * a.w +
               b.x * b.x + b.y * b.y + b.z * b.z + b.w * b.w;
    #pragma unroll
    for (int o = 16; o > 0; o >>= 1) {
        s1 += __shfl_xor_sync(0xFFFFFFFFu, s1, o);
        s2 += __shfl_xor_sync(0xFFFFFFFFu, s2, o);
    }
    float mu = s1 * (1.f / D_);
    float rstd = rsqrtf(s2 * (1.f / D_) - mu * mu + 1e-5f);
    float va[8] = {a.x, a.y, a.z, a.w, b.x, b.y, b.z, b.w};
    #pragma unroll
    for (int i = 0; i < 8; i++) {
        int c = (i < 4) ? (lane * 4 + i) : (128 + lane * 4 + i - 4);
        float y = (va[i] - mu) * rstd * gam[c] + bet[c];
        __nv_bfloat16 hi = __float2bfloat16(y);
        __nv_bfloat16 lo = __float2bfloat16(y - __bfloat162float(hi));
        g_mnh[(size_t)row * D_ + c] = hi;
        g_mnl[(size_t)row * D_ + c] = lo;
    }
}

// ---------------- mma.sync GEMM: C[128x64] = A[128x256] * B[64x256]^T ------
// bf16x3 (hi*hi + hi*lo + lo*hi), fp32 accumulators.
// 2-stage cp.async software pipeline, k-chunk = 32, 2 CTAs/SM.
#define PK 40                               // padded halves per 32-col row
#define ST_AH 0
#define ST_AL (128 * PK)
#define ST_BH (256 * PK)
#define ST_BL (320 * PK)
#define STAGE_H (384 * PK)                  // 15360 halves = 30720 B
#define SM_GEMM_BYTES (2 * STAGE_H * 2)     // 61440 B

__global__ __launch_bounds__(256, 2) void gemm_kernel(
    const __nv_bfloat16* __restrict__ Ah, const __nv_bfloat16* __restrict__ Al,
    const __nv_bfloat16* __restrict__ Bh, const __nv_bfloat16* __restrict__ Bl,
    const float* __restrict__ bias, float* __restrict__ outp, int mode) {
    extern __shared__ __align__(16) __nv_bfloat16 sm[];
    uint32_t smb = smem_u32(sm);
    int tid = threadIdx.x;
    int wid = tid >> 5, lane = tid & 31;
    int wm = wid & 3, wn = wid >> 2;
    int bm = blockIdx.y * 128;
    int bn0 = blockIdx.x * 64;

    const __nv_bfloat16* A0 = Ah + (size_t)bm * D_;
    const __nv_bfloat16* A1 = Al + (size_t)bm * D_;
    const __nv_bfloat16* B0 = Bh + (size_t)bn0 * D_;
    const __nv_bfloat16* B1 = Bl + (size_t)bn0 * D_;

    float acc[2][4][4];
    #pragma unroll
    for (int i = 0; i < 2; i++)
        #pragma unroll
        for (int f = 0; f < 4; f++)
            #pragma unroll
            for (int e = 0; e < 4; e++) acc[i][f][e] = 0.f;

    uint32_t aKof = (lane >> 4) * 8;
    uint32_t bN = (lane & 7) + ((lane >> 4) << 3);
    uint32_t bKof = ((lane >> 3) & 1) * 8;

    // fill stage `st` with k-chunk at k0 (6 cp16 per thread)
    auto fill = [&](int st, int k0) {
        uint32_t base = smb + (uint32_t)st * (STAGE_H * 2);
        #pragma unroll
        for (int t = 0; t < 2; t++) {
            int i = tid + t * 256;          // 0..511
            int r = i >> 2, sg = i & 3;
            uint32_t d = base + (uint32_t)(r * PK + sg * 8) * 2;
            const __nv_bfloat16* s = A0 + (size_t)r * D_ + k0 + sg * 8;
            cp16(d + ST_AH * 2, s);
            cp16(d + ST_AL * 2, A1 + (s - A0));
        }
        {
            int r = tid >> 2, sg = tid & 3;
            uint32_t d = base + (uint32_t)(r * PK + sg * 8) * 2;
            const __nv_bfloat16* s = B0 + (size_t)r * D_ + k0 + sg * 8;
            cp16(d + ST_BH * 2, s);
            cp16(d + ST_BL * 2, B1 + (s - B0));
        }
    };

    fill(0, 0);
    CP_COMMIT();
    CP_WAIT0();
    __syncthreads();

    #pragma unroll
    for (int c = 0; c < 8; c++) {
        if (c < 7) { fill((c + 1) & 1, (c + 1) * 32); CP_COMMIT(); }
        uint32_t base = smb + (uint32_t)(c & 1) * (STAGE_H * 2);
        #pragma unroll
        for (int ks = 0; ks < 2; ks++) {
            uint32_t ah[2][4], al[2][4], bh[2][4], bl[2][4];
            #pragma unroll
            for (int mf = 0; mf < 2; mf++) {
                uint32_t r = wm * 32 + mf * 16 + (lane & 15);
                uint32_t off = (r * PK + ks * 16 + aKof) * 2;
                ldsm4(ah[mf], base + ST_AH * 2 + off);
                ldsm4(al[mf], base + ST_AL * 2 + off);
            }
            #pragma unroll
            for (int bf = 0; bf < 2; bf++) {
                uint32_t r = wn * 32 + bf * 16 + bN;
                uint32_t off = (r * PK + ks * 16 + bKof) * 2;
                ldsm4(bh[bf], base + ST_BH * 2 + off);
                ldsm4(bl[bf], base + ST_BL * 2 + off);
            }
            #pragma unroll
            for (int mf = 0; mf < 2; mf++)
                #pragma unroll
                for (int bf = 0; bf < 2; bf++) {
                    mma_bf16(acc[mf][bf * 2 + 0], ah[mf], bh[bf][0], bh[bf][1]);
                    mma_bf16(acc[mf][bf * 2 + 1], ah[mf], bh[bf][2], bh[bf][3]);
                    mma_bf16(acc[mf][bf * 2 + 0], ah[mf], bl[bf][0], bl[bf][1]);
                    mma_bf16(acc[mf][bf * 2 + 1], ah[mf], bl[bf][2], bl[bf][3]);
                    mma_bf16(acc[mf][bf * 2 + 0], al[mf], bh[bf][0], bh[bf][1]);
                    mma_bf16(acc[mf][bf * 2 + 1], al[mf], bh[bf][2], bh[bf][3]);
                }
        }
        if (c < 7) CP_WAIT0();
        __syncthreads();
    }

    // --- epilogue
    if (mode == 0) {
        int t = bn0 >> 8;
        #pragma unroll
        for (int mf = 0; mf < 2; mf++)
            #pragma unroll
            for (int f = 0; f < 4; f++) {
                int bf = f >> 1, half = f & 1;
                int rr = bm + wm * 32 + mf * 16 + (lane >> 2);
                int cc = bn0 + wn * 32 + bf * 16 + half * 8 + (lane & 3) * 2;
                int jj = cc & 255;
                int hh = jj >> 5, ch = jj & 31;
                float v0 = acc[mf][f][0], v1 = acc[mf][f][1];   // row rr
                float v2 = acc[mf][f][2], v3 = acc[mf][f][3];   // row rr+8
                #pragma unroll
                for (int rp = 0; rp < 2; rp++) {
                    int rrow = rr + rp * 8;
                    int s = rrow >> 8, l = rrow & 255;
                    float a0 = rp ? v2 : v0, a1 = rp ? v3 : v1;
                    size_t shb = (size_t)(s * H_ + hh);
                    if (t == 0) {
                        split_store_pair(g_qh, g_ql, (shb * L_ + l) * C_ + ch,
                                         a0 * QSCALE, a1 * QSCALE);
                    } else if (t == 1) {
                        split_store_pair(g_kh, g_kl, (shb * L_ + l) * C_ + ch, a0, a1);
                    } else if (t == 2) {
                        size_t i0 = (shb * C_ + ch) * L_ + l;      // transposed
                        float h0 = __bfloat162float(__float2bfloat16(a0));
                        float h1 = __bfloat162float(__float2bfloat16(a1));
                        g_vth[i0] = __float2bfloat16(a0);
                        g_vtl[i0] = __float2bfloat16(a0 - h0);
                        g_vth[i0 + L_] = __float2bfloat16(a1);
                        g_vtl[i0 + L_] = __float2bfloat16(a1 - h1);
                    } else {
                        size_t i0 = (shb * L_ + l) * C_ + ch;
                        g_g[i0] = 1.f / (1.f + fast_exp2(-(a0 + bias[jj]) * LOG2E));
                        g_g[i0 + 1] = 1.f / (1.f + fast_exp2(-(a1 + bias[jj + 1]) * LOG2E));
                    }
                }
            }
    } else {
        #pragma unroll
        for (int mf = 0; mf < 2; mf++)
            #pragma unroll
            for (int f = 0; f < 4; f++) {
                int bf = f >> 1, half = f & 1;
                #pragma unroll
                for (int e = 0; e < 4; e++) {
                    int rr = bm + wm * 32 + mf * 16 + (lane >> 2) + (e >> 1) * 8;
                    int cc = bn0 + wn * 32 + bf * 16 + half * 8 + (lane & 3) * 2 + (e & 1);
                    outp[(size_t)rr * D_ + cc] = acc[mf][f][e] + bias[cc];
                }
            }
    }
}

// ---------------- Tensor-core attention: one block per (s,h) ---------------
#define KPAD 40                        // halves per K row (32 + 8 pad)
#define VPAD 264                       // halves per Vt row (256 + 8 pad)
#define ATT_BCOL 0                     // float[256]            : 1024 B
#define ATT_KH  1024                   // bf16 [256][KPAD]      : 20480 B
#define ATT_KL  (ATT_KH + 20480)
#define ATT_VH  (ATT_KL + 20480)       // bf16 [32][VPAD]       : 16896 B
#define ATT_VL  (ATT_VH + 16896)
#define ATT_SMEM (ATT_VL + 16896)      // 75776 B

__global__ __launch_bounds__(512, 1) void attn_kernel() {
    extern __shared__ __align__(16) char asm_[];
    uint32_t smb = smem_u32(asm_);
    float* bc = (float*)(asm_ + ATT_BCOL);
    int sh = blockIdx.x;
    int s = sh >> 3, h = sh & 7;
    size_t base = (size_t)sh * (L_ * C_);
    int tid = threadIdx.x;
    int wid = tid >> 5, lane = tid & 31;

    // stage K hi/lo and Vt hi/lo via cp.async (8 x 16B per thread)
    #pragma unroll
    for (int t = 0; t < 2; t++) {
        int i = tid + t * 512;
        int r = i >> 2, sg = (i & 3) * 8;
        uint32_t d = smb + ATT_KH + (uint32_t)(r * KPAD + sg) * 2;
        cp16(d, g_kh + base + r * 32 + sg);
        cp16(d + 20480, g_kl + base + r * 32 + sg);
        int rv = i >> 5, sgv = (i & 31) * 8;
        uint32_t dv = smb + ATT_VH + (uint32_t)(rv * VPAD + sgv) * 2;
        cp16(dv, g_vth + base + rv * 256 + sgv);
        cp16(dv + 16896, g_vtl + base + rv * 256 + sgv);
    }
    if (tid < 256) bc[tid] = (g_rp[tid] != 0.f) ? NEG_BIAS2 : 0.f;
    CP_COMMIT();
    CP_WAIT0();
    __syncthreads();

    int g4 = lane >> 2, t4 = lane & 3;
    int rowA = wid * 16 + g4;              // q rows rowA, rowA+8
    bool mA = (g_sp[rowA] != 0.f);
    bool mB = (g_sp[rowA + 8] != 0.f);

    // Q A-fragments via direct LDG (hi, lo), 2 k16 steps
    uint32_t qh[2][4], ql[2][4];
    {
        const __nv_bfloat16* q0 = g_qh + base + (size_t)rowA * 32;
        const __nv_bfloat16* q1 = g_ql + base + (size_t)rowA * 32;
        #pragma unroll
        for (int ks = 0; ks < 2; ks++) {
            int c0 = ks * 16 + 2 * t4;
            qh[ks][0] = *(const uint32_t*)(q0 + c0);
            qh[ks][1] = *(const uint32_t*)(q0 + 8 * 32 + c0);
            qh[ks][2] = *(const uint32_t*)(q0 + c0 + 8);
            qh[ks][3] = *(const uint32_t*)(q0 + 8 * 32 + c0 + 8);
            ql[ks][0] = *(const uint32_t*)(q1 + c0);
            ql[ks][1] = *(const uint32_t*)(q1 + 8 * 32 + c0);
            ql[ks][2] = *(const uint32_t*)(q1 + c0 + 8);
            ql[ks][3] = *(const uint32_t*)(q1 + 8 * 32 + c0 + 8);
        }
    }

    float o[4][4];
    #pragma unroll
    for (int f = 0; f < 4; f++)
        #pragma unroll
        for (int e = 0; e < 4; e++) o[f][e] = 0.f;
    float rs0 = 0.f, rs1 = 0.f;

    uint32_t bN = (lane & 7) + ((lane >> 4) << 3);
    uint32_t bKof = ((lane >> 3) & 1) * 8;

    #pragma unroll
    for (int chunk = 0; chunk < 4; chunk++) {
        int j0 = chunk * 64;
        float S[8][4];
        #pragma unroll
        for (int f = 0; f < 8; f++)
            #pragma unroll
            for (int e = 0; e < 4; e++) S[f][e] = 0.f;

        // S = Q K^T  (3-pass bf16)
        #pragma unroll
        for (int ks = 0; ks < 2; ks++)
            #pragma unroll
            for (int nf = 0; nf < 4; nf++) {
                uint32_t kh4[4], kl4[4];
                uint32_t addr = smb + ATT_KH +
                    ((uint32_t)(j0 + nf * 16 + bN) * KPAD + ks * 16 + bKof) * 2;
                ldsm4(kh4, addr);
                ldsm4(kl4, addr + 20480);
                mma_bf16(S[nf * 2 + 0], qh[ks], kh4[0], kh4[1]);
                mma_bf16(S[nf * 2 + 1], qh[ks], kh4[2], kh4[3]);
                mma_bf16(S[nf * 2 + 0], qh[ks], kl4[0], kl4[1]);
                mma_bf16(S[nf * 2 + 1], qh[ks], kl4[2], kl4[3]);
                mma_bf16(S[nf * 2 + 0], ql[ks], kh4[0], kh4[1]);
                mma_bf16(S[nf * 2 + 1], ql[ks], kh4[2], kh4[3]);
            }

        // bias + exp2 + pack into P A-frags (hi, lo)
        uint32_t ph[4][4], plo[4][4];
        #pragma unroll
        for (int f = 0; f < 8; f++) {
            int j = j0 + f * 8 + 2 * t4;
            float b0 = bc[j], b1 = bc[j + 1];
            float p0 = fast_exp2(S[f][0] + (mA ? 0.f : b0));
            float p1 = fast_exp2(S[f][1] + (mA ? 0.f : b1));
            float p2 = fast_exp2(S[f][2] + (mB ? 0.f : b0));
            float p3 = fast_exp2(S[f][3] + (mB ? 0.f : b1));
            rs0 += p0 + p1;
            rs1 += p2 + p3;
            float h0 = __bfloat162float(__float2bfloat16(p0));
            float h1 = __bfloat162float(__float2bfloat16(p1));
            float h2 = __bfloat162float(__float2bfloat16(p2));
            float h3 = __bfloat162float(__float2bfloat16(p3));
            int f2 = f >> 1, off = (f & 1) * 2;
            ph[f2][off + 0] = pack_bf16x2(p0, p1);
            ph[f2][off + 1] = pack_bf16x2(p2, p3);
            plo[f2][off + 0] = pack_bf16x2(p0 - h0, p1 - h1);
            plo[f2][off + 1] = pack_bf16x2(p2 - h2, p3 - h3);
        }

        // O += P * V^T  (3-pass: ph*vh + ph*vl + plo*vh)
        #pragma unroll
        for (int f2 = 0; f2 < 4; f2++)
            #pragma unroll
            for (int ng = 0; ng < 2; ng++) {
                uint32_t vh4[4], vl4[4];
                uint32_t vaddr = smb + ATT_VH +
                    ((uint32_t)(ng * 16 + bN) * VPAD + j0 + f2 * 16 + bKof) * 2;
                ldsm4(vh4, vaddr);
                ldsm4(vl4, vaddr + 16896);
                mma_bf16(o[ng * 2 + 0], ph[f2], vh4[0], vh4[1]);
                mma_bf16(o[ng * 2 + 1], ph[f2], vh4[2], vh4[3]);
                mma_bf16(o[ng * 2 + 0], ph[f2], vl4[0], vl4[1]);
                mma_bf16(o[ng * 2 + 1], ph[f2], vl4[2], vl4[3]);
                mma_bf16(o[ng * 2 + 0], plo[f2], vh4[0], vh4[1]);
                mma_bf16(o[ng * 2 + 1], plo[f2], vh4[2], vh4[3]);
            }
    }

    // row-sum reduce across the 4 lanes sharing each row
    rs0 += __shfl_xor_sync(0xFFFFFFFFu, rs0, 1);
    rs0 += __shfl_xor_sync(0xFFFFFFFFu, rs0, 2);
    rs1 += __shfl_xor_sync(0xFFFFFFFFu, rs1, 1);
    rs1 += __shfl_xor_sync(0xFFFFFFFFu, rs1, 2);
    float inv0 = 1.f / rs0, inv1 = 1.f / rs1;

    // epilogue: normalize, gate, split to bf16 hi/lo
    #pragma unroll
    for (int nf = 0; nf < 4; nf++) {
        int c = nf * 8 + 2 * t4;
        float2 ga = *(const float2*)(g_g + base + (size_t)rowA * 32 + c);
        float2 gb = *(const float2*)(g_g + base + (size_t)(rowA + 8) * 32 + c);
        float v0 = o[nf][0] * inv0 * ga.x;
        float v1 = o[nf][1] * inv0 * ga.y;
        float v2 = o[nf][2] * inv1 * gb.x;
        float v3 = o[nf][3] * inv1 * gb.y;
        size_t oA = ((size_t)(s * L_ + rowA)) * D_ + h * 32 + c;
        size_t oB = ((size_t)(s * L_ + rowA + 8)) * D_ + h * 32 + c;
        split_store_pair(g_oh, g_ol, oA, v0, v1);
        split_store_pair(g_oh, g_ol, oB, v2, v3);
    }
}

// ---------------- launch ---------------------------------------------------
extern "C" void kernel_launch(void* const* d_in, const int* in_sizes, int n_in,
                              void* d_out, int out_size) {
    const float* m    = (const float*)d_in[0];
    const void*  spad = d_in[1];
    const void*  rpad = d_in[2];
    const float* ln_g = (const float*)d_in[3];
    const float* ln_b = (const float*)d_in[4];
    const float* Wq   = (const float*)d_in[5];
    const float* Wk   = (const float*)d_in[6];
    const float* Wv   = (const float*)d_in[7];
    const float* Wg   = (const float*)d_in[8];
    const float* bg   = (const float*)d_in[9];
    const float* Wo   = (const float*)d_in[10];
    const float* bo   = (const float*)d_in[11];
    float* out = (float*)d_out;

    static int smem_set = 0;
    if (!smem_set) {
        cudaFuncSetAttribute(gemm_kernel, cudaFuncAttributeMaxDynamicSharedMemorySize,
                             SM_GEMM_BYTES);
        cudaFuncSetAttribute(attn_kernel, cudaFuncAttributeMaxDynamicSharedMemorySize,
                             ATT_SMEM);
        smem_set = 1;
    }

    prep_mask_kernel<<<1, 256>>>(spad, rpad);
    prep_w_kernel<<<5 * 256, 256>>>(Wq, Wk, Wv, Wg, Wo);
    ln_kernel<<<MROWS / 8, 256>>>(m, ln_g, ln_b);

    __nv_bfloat16 *mh, *ml, *wh, *wl, *oh, *ol;
    cudaGetSymbolAddress((void**)&mh, g_mnh);
    cudaGetSymbolAddress((void**)&ml, g_mnl);
    cudaGetSymbolAddress((void**)&wh, g_wh);
    cudaGetSymbolAddress((void**)&wl, g_wl);
    cudaGetSymbolAddress((void**)&oh, g_oh);
    cudaGetSymbolAddress((void**)&ol, g_ol);

    dim3 gp(16, MROWS / 128);   // proj: N = [Wq|Wk|Wv|Wg]
    gemm_kernel<<<gp, 256, SM_GEMM_BYTES>>>(mh, ml, wh, wl, bg, nullptr, 0);

    attn_kernel<<<S_ * H_, 512, ATT_SMEM>>>();

    dim3 go(4, MROWS / 128);    // out projection
    gemm_kernel<<<go, 256, SM_GEMM_BYTES>>>(oh, ol, wh + 4 * D_ * D_,
                                            wl + 4 * D_ * D_, bo, out, 1);
}